// round 10
// baseline (speedup 1.0000x reference)
#include <cuda_runtime.h>

// out[b,e] = sparsity[b,e] * sum_h ( sum_m hidden[b,m,h] ) * ( sum_n weight[e,h,n] )
// A=1, B=32, M=32, H=1024, E=8, N=1024.
//
// SINGLE kernel, no inter-block waits. 512 blocks x 256 threads.
// Block (chunk, q): h0 = (bid>>2)*8, n-range = q*256..+256 (q = bid&3).
//   Phase H: load hidden[b, 4m, h0..h0+8) partials (issued FIRST, 8 LDG.128/thread)
//   Phase W: warp e sums its 8 weight rows over the n-quarter (16 LDG.128/lane)
//   Phase D: thread (b,e) dots 8 h's, RED into persistent g_accum[256].
//   Tail: last block (done counter) writes out = accum * sparsity, resets scratch.

#define Bn 32
#define Mn 32
#define Hn 1024
#define En 8
#define Nn 1024
#define NBLK 512

__device__ float g_accum[Bn * En];   // zero at load; reset by tail each run
__device__ int   g_done = 0;

__global__ void __launch_bounds__(256) einsum_fused_kernel(
    const float* __restrict__ hidden,
    const float* __restrict__ sparsity,
    const float* __restrict__ weight,
    float* __restrict__ out)
{
    const int tid  = threadIdx.x;
    const int lane = tid & 31;
    const int wid  = tid >> 5;          // = e for phase W
    const int bid  = blockIdx.x;
    const int h0   = (bid >> 2) * 8;    // h-chunk base (128 chunks)
    const int q    = bid & 3;           // n-quarter

    __shared__ float  sm_ws[8][8];      // ws[e][hh]
    __shared__ float4 sm_hp[32][8][2];  // per-(b, m-group) partials (8 h floats)
    __shared__ float  sm_hs[32][8];     // hs[b][hh]
    __shared__ int    sm_last;

    // ---- Phase H loads FIRST: thread (b = tid>>3, mg = tid&7), 4 m-rows x 8 h ----
    const int b  = tid >> 3;
    const int mg = tid & 7;
    const float4* H4 = reinterpret_cast<const float4*>(hidden);
    const size_t hbase = (size_t)(b * Mn + mg * 4) * (Hn / 4) + (h0 >> 2);
    float4 a0 = make_float4(0.f, 0.f, 0.f, 0.f);
    float4 a1 = make_float4(0.f, 0.f, 0.f, 0.f);
    #pragma unroll
    for (int mm = 0; mm < 4; mm++) {          // 8 independent LDG.128
        float4 v0 = H4[hbase + (size_t)mm * (Hn / 4)];
        float4 v1 = H4[hbase + (size_t)mm * (Hn / 4) + 1];
        a0.x += v0.x; a0.y += v0.y; a0.z += v0.z; a0.w += v0.w;
        a1.x += v1.x; a1.y += v1.y; a1.z += v1.z; a1.w += v1.w;
    }

    // ---- Phase W: warp `wid` = e; 8 rows x 256 floats (n-quarter) ----
    const float4* W4 = reinterpret_cast<const float4*>(weight);
    const size_t rowbase = (size_t)(wid * Hn + h0) * (Nn / 4) + q * 64 + lane;
    float s[8];
    #pragma unroll
    for (int hh = 0; hh < 8; hh++) {          // 16 LDG.128, 8 chains of 2
        float4 v0 = W4[rowbase + (size_t)hh * (Nn / 4)];
        float4 v1 = W4[rowbase + (size_t)hh * (Nn / 4) + 32];
        s[hh] = ((v0.x + v0.y) + (v0.z + v0.w)) + ((v1.x + v1.y) + (v1.z + v1.w));
    }

    // store H partials (waits only on H loads; W loads still in flight)
    sm_hp[b][mg][0] = a0;
    sm_hp[b][mg][1] = a1;

    // W warp reduce
    #pragma unroll
    for (int off = 16; off > 0; off >>= 1)
        #pragma unroll
        for (int hh = 0; hh < 8; hh++)
            s[hh] += __shfl_xor_sync(0xffffffffu, s[hh], off);
    if (lane == 0) {
        #pragma unroll
        for (int hh = 0; hh < 8; hh++) sm_ws[wid][hh] = s[hh];
    }
    __syncthreads();

    // reduce over m-groups: thread (b, hh) sums 8 partials
    {
        const int bb = tid >> 3;
        const int hh = tid & 7;
        float hs = 0.f;
        #pragma unroll
        for (int g = 0; g < 8; g++)
            hs += reinterpret_cast<const float*>(&sm_hp[bb][g][0])[hh];
        sm_hs[bb][hh] = hs;
    }
    __syncthreads();

    // ---- Phase D: thread (b = tid>>3, e = tid&7), RED into g_accum ----
    {
        const int bb = tid >> 3;
        const int e  = tid & 7;
        float p = 0.f;
        #pragma unroll
        for (int hh = 0; hh < 8; hh++)
            p += sm_hs[bb][hh] * sm_ws[e][hh];
        atomicAdd(&g_accum[tid], p);          // index = bb*8+e = tid
    }

    // ---- Tail: last block finalizes ----
    __threadfence();
    __syncthreads();
    if (tid == 0)
        sm_last = (atomicAdd(&g_done, 1) == NBLK - 1) ? 1 : 0;
    __syncthreads();
    if (sm_last) {
        __threadfence();
        const float v = __ldcg(&g_accum[tid]);
        out[tid] = v * sparsity[tid];
        g_accum[tid] = 0.f;                   // reset for next graph replay
        if (tid == 0) g_done = 0;
    }
}

extern "C" void kernel_launch(void* const* d_in, const int* in_sizes, int n_in,
                              void* d_out, int out_size)
{
    const float* hidden   = (const float*)d_in[0];
    const float* sparsity = (const float*)d_in[1];
    const float* weight   = (const float*)d_in[2];
    float* out = (float*)d_out;

    einsum_fused_kernel<<<NBLK, 256>>>(hidden, sparsity, weight, out);
}

// round 11
// speedup vs baseline: 1.0979x; 1.0979x over previous
#include <cuda_runtime.h>

// out[b,e] = sparsity[b,e] * sum_h ( sum_m hidden[b,m,h] ) * ( sum_n weight[e,h,n] )
// A=1, B=32, M=32, H=1024, E=8, N=1024.
//
// SINGLE kernel. 512 blocks x 256 threads = (256 h-chunks of 4) x (2 n-halves).
// Hidden duplication: 2x (fits L2). ONE __syncthreads in the main path.
//   Phase H: thread (b,mg) sums 4 m-rows of 1 float4 (4 h) -> smem partials.
//   Phase W: warp e streams 4 weight rows x 512 floats (16 indep LDG.128),
//            shfl-reduce -> smem ws[e][0..3].
//   Phase D: thread (b,e) folds mg-sum into dot, RED into persistent g_accum.
//   Tail: last block (done counter) writes out = accum * sparsity, resets.

#define Bn 32
#define Mn 32
#define Hn 1024
#define En 8
#define Nn 1024
#define NBLK 512

__device__ float g_accum[Bn * En];   // zeroed at load; reset by tail each run
__device__ int   g_done = 0;

__global__ void __launch_bounds__(256) einsum_fused_kernel(
    const float* __restrict__ hidden,
    const float* __restrict__ sparsity,
    const float* __restrict__ weight,
    float* __restrict__ out)
{
    const int tid  = threadIdx.x;
    const int lane = tid & 31;
    const int wid  = tid >> 5;           // = e for phase W
    const int bid  = blockIdx.x;
    const int chunk = bid >> 1;          // [0,256): 4 h's each
    const int half  = bid & 1;           // n-half
    const int h0    = chunk * 4;

    __shared__ float4 sm_hp[8][32];      // [mg][b] partial over 4 m-rows (4 h floats)
    __shared__ float4 sm_ws4[8];         // ws[e][0..3]
    __shared__ int    sm_last;

    // ---- Phase H loads FIRST: thread (b = tid>>3, mg = tid&7), 4 m-rows x 4 h ----
    const int b  = tid >> 3;
    const int mg = tid & 7;
    const float4* H4 = reinterpret_cast<const float4*>(hidden);
    const size_t hbase = (size_t)(b * Mn + mg * 4) * (Hn / 4) + chunk;
    float4 a = make_float4(0.f, 0.f, 0.f, 0.f);
    {
        float4 v0 = H4[hbase];
        float4 v1 = H4[hbase + (Hn / 4)];
        float4 v2 = H4[hbase + 2 * (Hn / 4)];
        float4 v3 = H4[hbase + 3 * (Hn / 4)];
        a.x = ((v0.x + v1.x) + (v2.x + v3.x));
        a.y = ((v0.y + v1.y) + (v2.y + v3.y));
        a.z = ((v0.z + v1.z) + (v2.z + v3.z));
        a.w = ((v0.w + v1.w) + (v2.w + v3.w));
    }

    // ---- Phase W: warp e = wid; 4 rows x 512 floats (n-half), 16 indep LDG.128 ----
    const float4* W4 = reinterpret_cast<const float4*>(weight);
    const size_t rowbase = (size_t)(wid * Hn + h0) * (Nn / 4) + half * 128 + lane;
    float s0, s1, s2, s3;
    {
        float4 v00 = W4[rowbase + 0];
        float4 v01 = W4[rowbase + 32];
        float4 v02 = W4[rowbase + 64];
        float4 v03 = W4[rowbase + 96];
        float4 v10 = W4[rowbase + (Nn / 4) + 0];
        float4 v11 = W4[rowbase + (Nn / 4) + 32];
        float4 v12 = W4[rowbase + (Nn / 4) + 64];
        float4 v13 = W4[rowbase + (Nn / 4) + 96];
        float4 v20 = W4[rowbase + 2 * (Nn / 4) + 0];
        float4 v21 = W4[rowbase + 2 * (Nn / 4) + 32];
        float4 v22 = W4[rowbase + 2 * (Nn / 4) + 64];
        float4 v23 = W4[rowbase + 2 * (Nn / 4) + 96];
        float4 v30 = W4[rowbase + 3 * (Nn / 4) + 0];
        float4 v31 = W4[rowbase + 3 * (Nn / 4) + 32];
        float4 v32 = W4[rowbase + 3 * (Nn / 4) + 64];
        float4 v33 = W4[rowbase + 3 * (Nn / 4) + 96];
        s0 = (((v00.x + v00.y) + (v00.z + v00.w)) + ((v01.x + v01.y) + (v01.z + v01.w)))
           + (((v02.x + v02.y) + (v02.z + v02.w)) + ((v03.x + v03.y) + (v03.z + v03.w)));
        s1 = (((v10.x + v10.y) + (v10.z + v10.w)) + ((v11.x + v11.y) + (v11.z + v11.w)))
           + (((v12.x + v12.y) + (v12.z + v12.w)) + ((v13.x + v13.y) + (v13.z + v13.w)));
        s2 = (((v20.x + v20.y) + (v20.z + v20.w)) + ((v21.x + v21.y) + (v21.z + v21.w)))
           + (((v22.x + v22.y) + (v22.z + v22.w)) + ((v23.x + v23.y) + (v23.z + v23.w)));
        s3 = (((v30.x + v30.y) + (v30.z + v30.w)) + ((v31.x + v31.y) + (v31.z + v31.w)))
           + (((v32.x + v32.y) + (v32.z + v32.w)) + ((v33.x + v33.y) + (v33.z + v33.w)));
    }

    // hidden partial -> smem (independent of W loads still in flight)
    sm_hp[mg][b] = a;

    #pragma unroll
    for (int off = 16; off > 0; off >>= 1) {
        s0 += __shfl_xor_sync(0xffffffffu, s0, off);
        s1 += __shfl_xor_sync(0xffffffffu, s1, off);
        s2 += __shfl_xor_sync(0xffffffffu, s2, off);
        s3 += __shfl_xor_sync(0xffffffffu, s3, off);
    }
    if (lane == 0) sm_ws4[wid] = make_float4(s0, s1, s2, s3);

    __syncthreads();    // the ONE barrier in the main path

    // ---- Phase D: thread (b = tid>>3, e = tid&7): fold mg-sum into dot ----
    {
        const int e = tid & 7;
        const float4 w = sm_ws4[e];
        float p = 0.f;
        #pragma unroll
        for (int g = 0; g < 8; g++) {
            float4 v = sm_hp[g][b];
            p += v.x * w.x + v.y * w.y + v.z * w.z + v.w * w.w;
        }
        atomicAdd(&g_accum[tid], p);    // index = b*8+e = tid
    }

    // ---- Tail: last block finalizes ----
    __threadfence();
    __syncthreads();
    if (tid == 0)
        sm_last = (atomicAdd(&g_done, 1) == NBLK - 1) ? 1 : 0;
    __syncthreads();
    if (sm_last) {
        __threadfence();
        const float v = __ldcg(&g_accum[tid]);
        out[tid] = v * sparsity[tid];
        g_accum[tid] = 0.f;             // reset for next graph replay
        if (tid == 0) g_done = 0;
    }
}

extern "C" void kernel_launch(void* const* d_in, const int* in_sizes, int n_in,
                              void* d_out, int out_size)
{
    const float* hidden   = (const float*)d_in[0];
    const float* sparsity = (const float*)d_in[1];
    const float* weight   = (const float*)d_in[2];
    float* out = (float*)d_out;

    einsum_fused_kernel<<<NBLK, 256>>>(hidden, sparsity, weight, out);
}

// round 12
// speedup vs baseline: 1.3175x; 1.2000x over previous
#include <cuda_runtime.h>

// out[b,e] = sparsity[b,e] * sum_h ( sum_m hidden[b,m,h] ) * ( sum_n weight[e,h,n] )
// A=1, B=32, M=32, H=1024, E=8, N=1024.
//
// SINGLE kernel, ONE wave, ZERO duplication: 128 blocks x 256 threads.
// Block = h-chunk of 8 (owns ALL n for its 8 h's, and all of hidden's 8-h slice).
//   Phase H (issued first): thread sums an 8-m group of one b over its 8-h slice
//            (lane-paired float4 -> 16 wavefronts/warp-load), partials -> smem.
//   Phase W: warp e streams 8 full weight rows, 8 batches x 8 independent LDG.128
//            (8 accumulator chains -> MLP~8 sustained across whole block).
//   Phase D: thread (b,e) dot over 8 h (mg-fold in registers), 1 RED -> g_accum.
//   Tail: last block writes out = accum * sparsity, resets scratch.

#define Bn 32
#define Mn 32
#define Hn 1024
#define En 8
#define Nn 1024
#define NBLK (Hn / 8)    // 128

__device__ float g_accum[Bn * En];   // zeroed at load; reset by tail each run
__device__ int   g_done = 0;

__global__ void __launch_bounds__(256) einsum_fused_kernel(
    const float* __restrict__ hidden,
    const float* __restrict__ sparsity,
    const float* __restrict__ weight,
    float* __restrict__ out)
{
    const int tid  = threadIdx.x;
    const int lane = tid & 31;
    const int wid  = tid >> 5;          // = e for phase W
    const int bid  = blockIdx.x;
    const int h0   = bid * 8;

    __shared__ float4 sm_hp[32][4][2];  // [b][mg][f4]: partial over 8 m-rows (4 h each)
    __shared__ float4 sm_ws[8][2];      // ws[e][f4]
    __shared__ int    sm_last;

    // ---- Phase H FIRST: thread pair shares an 8-m group of one b ----
    // b = tid>>3, mg = (tid>>1)&3 (8 m's), f4 = tid&1 (which half of the 8 h's).
    // Lane-paired addresses: adjacent lanes read adjacent float4 (16 lines/warp-LDG).
    {
        const int rowbase = (tid >> 1) * 8;       // = b*32 + mg*8
        const int f4      = tid & 1;
        const float4* H4  = reinterpret_cast<const float4*>(hidden);
        const size_t base = (size_t)rowbase * (Hn / 4) + (h0 >> 2) + f4;
        float4 a = make_float4(0.f, 0.f, 0.f, 0.f);
        #pragma unroll
        for (int j = 0; j < 8; j++) {             // 8 independent LDG.128
            float4 v = H4[base + (size_t)j * (Hn / 4)];
            a.x += v.x; a.y += v.y; a.z += v.z; a.w += v.w;
        }
        sm_hp[tid >> 3][(tid >> 1) & 3][f4] = a;
    }

    // ---- Phase W: warp e streams rows (e, h0..h0+8), all 1024 n ----
    float s[8] = {0.f, 0.f, 0.f, 0.f, 0.f, 0.f, 0.f, 0.f};
    {
        const float4* W4 = reinterpret_cast<const float4*>(weight);
        const size_t rb  = (size_t)(wid * Hn + h0) * (Nn / 4) + lane;
        #pragma unroll
        for (int k = 0; k < 8; k++) {             // 8 batches
            float4 v[8];
            #pragma unroll
            for (int hh = 0; hh < 8; hh++)        // 8 independent LDG.128 per batch
                v[hh] = W4[rb + (size_t)hh * (Nn / 4) + k * 32];
            #pragma unroll
            for (int hh = 0; hh < 8; hh++)
                s[hh] += (v[hh].x + v[hh].y) + (v[hh].z + v[hh].w);
        }
        #pragma unroll
        for (int off = 16; off > 0; off >>= 1)
            #pragma unroll
            for (int hh = 0; hh < 8; hh++)
                s[hh] += __shfl_xor_sync(0xffffffffu, s[hh], off);
        if (lane == 0) {
            sm_ws[wid][0] = make_float4(s[0], s[1], s[2], s[3]);
            sm_ws[wid][1] = make_float4(s[4], s[5], s[6], s[7]);
        }
    }
    __syncthreads();    // the ONE barrier in the main path

    // ---- Phase D: thread (b = tid>>3, e = tid&7), fold mg-sum into dot ----
    {
        const int b = tid >> 3;
        const int e = tid & 7;
        const float4 w0 = sm_ws[e][0];
        const float4 w1 = sm_ws[e][1];
        float p = 0.f;
        #pragma unroll
        for (int g = 0; g < 4; g++) {
            float4 v0 = sm_hp[b][g][0];
            float4 v1 = sm_hp[b][g][1];
            p += v0.x * w0.x + v0.y * w0.y + v0.z * w0.z + v0.w * w0.w
               + v1.x * w1.x + v1.y * w1.y + v1.z * w1.z + v1.w * w1.w;
        }
        atomicAdd(&g_accum[tid], p);    // index = b*8+e = tid
    }

    // ---- Tail: last block finalizes ----
    __threadfence();
    __syncthreads();
    if (tid == 0)
        sm_last = (atomicAdd(&g_done, 1) == NBLK - 1) ? 1 : 0;
    __syncthreads();
    if (sm_last) {
        __threadfence();
        const float v = __ldcg(&g_accum[tid]);
        out[tid] = v * sparsity[tid];
        g_accum[tid] = 0.f;             // reset for next graph replay
        if (tid == 0) g_done = 0;
    }
}

extern "C" void kernel_launch(void* const* d_in, const int* in_sizes, int n_in,
                              void* d_out, int out_size)
{
    const float* hidden   = (const float*)d_in[0];
    const float* sparsity = (const float*)d_in[1];
    const float* weight   = (const float*)d_in[2];
    float* out = (float*)d_out;

    einsum_fused_kernel<<<NBLK, 256>>>(hidden, sparsity, weight, out);
}